// round 3
// baseline (speedup 1.0000x reference)
#include <cuda_runtime.h>

// Problem constants
#define Bb 4
#define Tt 4096
#define Ee 768
#define Dd 64
#define NROW (Bb*Tt)   // 16384

// Scratch for projected Q / K_arg / V_arg (static device globals: no runtime alloc)
__device__ float g_q[NROW*Dd];
__device__ float g_k[NROW*Dd];
__device__ float g_v[NROW*Dd];

// ---------------------------------------------------------------------------
// Fused projection: computes q = x@Wq+bq, k_arg = x@Wv+bv, v_arg = x@Wk+bk
// (reference swaps K/V weights). Grid: (NROW/128, 3), 256 threads.
// Block computes 128 rows x 64 cols of one of the three outputs.
// ---------------------------------------------------------------------------
#define RB 128
#define KC 32

__global__ __launch_bounds__(256) void proj_kernel(
    const float* __restrict__ x,
    const float* __restrict__ Wq, const float* __restrict__ bq,
    const float* __restrict__ Wk, const float* __restrict__ bk,
    const float* __restrict__ Wv, const float* __restrict__ bv)
{
    __shared__ float xs[KC][RB + 4];   // transposed: xs[k][row]
    __shared__ float ws[KC][Dd];       // ws[k][col]

    int m = blockIdx.y;
    const float* W    = (m == 0) ? Wq : ((m == 1) ? Wv : Wk);
    const float* bias = (m == 0) ? bq : ((m == 1) ? bv : bk);
    float* out        = (m == 0) ? g_q : ((m == 1) ? g_k : g_v);

    int row0 = blockIdx.x * RB;
    int tid  = threadIdx.x;
    int ty   = tid >> 4;      // 0..15 -> 8 rows each
    int tx   = tid & 15;      // 0..15 -> 4 cols each

    float acc[8][4];
    #pragma unroll
    for (int r = 0; r < 8; r++)
        #pragma unroll
        for (int c = 0; c < 4; c++) acc[r][c] = 0.f;

    for (int e0 = 0; e0 < Ee; e0 += KC) {
        __syncthreads();
        // load x chunk [128 rows][32 k], transposed into smem
        #pragma unroll
        for (int i = 0; i < 16; i++) {
            int idx = tid + i * 256;            // 4096 = 128*32
            int k   = idx & (KC - 1);
            int row = idx >> 5;
            xs[k][row] = x[(size_t)(row0 + row) * Ee + e0 + k];
        }
        // load W chunk [32 k][64 cols]
        #pragma unroll
        for (int i = 0; i < 8; i++) {
            int idx = tid + i * 256;            // 2048 = 32*64
            int col = idx & 63;
            int k   = idx >> 6;
            ws[k][col] = W[(size_t)(e0 + k) * Dd + col];
        }
        __syncthreads();
        #pragma unroll
        for (int k = 0; k < KC; k++) {
            float4 wv4 = *(const float4*)&ws[k][tx * 4];
            float4 a0  = *(const float4*)&xs[k][ty * 8];
            float4 a1  = *(const float4*)&xs[k][ty * 8 + 4];
            float a[8] = {a0.x, a0.y, a0.z, a0.w, a1.x, a1.y, a1.z, a1.w};
            #pragma unroll
            for (int r = 0; r < 8; r++) {
                acc[r][0] += a[r] * wv4.x;
                acc[r][1] += a[r] * wv4.y;
                acc[r][2] += a[r] * wv4.z;
                acc[r][3] += a[r] * wv4.w;
            }
        }
    }

    float b0 = bias[tx * 4 + 0], b1 = bias[tx * 4 + 1];
    float b2 = bias[tx * 4 + 2], b3 = bias[tx * 4 + 3];
    #pragma unroll
    for (int r = 0; r < 8; r++) {
        float4 o4 = make_float4(acc[r][0] + b0, acc[r][1] + b1,
                                acc[r][2] + b2, acc[r][3] + b3);
        *(float4*)&out[(size_t)(row0 + ty * 8 + r) * Dd + tx * 4] = o4;
    }
}

// ---------------------------------------------------------------------------
// Flash attention (fp32, online softmax). Grid: 256 blocks (4 batch x 64 row
// tiles of 64), 256 threads as 16x16. Each thread owns a 4x4 microtile.
// Smem layouts padded to 68 floats/row for conflict-free float4 access.
// ---------------------------------------------------------------------------
#define BM 64
#define BN 64
#define LDP 68
#define SMEM_ATTN (4 * 64 * LDP * 4)   // 69632 bytes

__global__ __launch_bounds__(256) void attn_kernel(float* __restrict__ out)
{
    extern __shared__ float sm[];
    float* qs = sm;                 // [64][LDP]  qs[k*LDP + i]  (transposed)
    float* ks = qs + 64 * LDP;      // [64][LDP]  ks[k*LDP + s]  (transposed)
    float* vs = ks + 64 * LDP;      // [64][LDP]  vs[s*LDP + d]
    float* ps = vs + 64 * LDP;      // [64][LDP]  ps[s*LDP + i]

    int bx    = blockIdx.x;
    int batch = bx >> 6;
    int row0  = (bx & 63) * BM;
    size_t qbase  = ((size_t)batch * Tt + row0) * Dd;
    size_t kvbase = (size_t)batch * Tt * Dd;

    int tid = threadIdx.x;
    int ty  = tid >> 4;   // 0..15 -> 4 q-rows
    int tx  = tid & 15;   // 0..15 -> 4 key cols / 4 d cols

    // load Q tile transposed
    #pragma unroll
    for (int i = 0; i < 16; i++) {
        int idx = tid + i * 256;
        int k = idx & 63, r = idx >> 6;
        qs[k * LDP + r] = g_q[qbase + (size_t)r * Dd + k];
    }

    float o[4][4], mrow[4], lrow[4];
    #pragma unroll
    for (int r = 0; r < 4; r++) {
        mrow[r] = -1e30f; lrow[r] = 0.f;
        #pragma unroll
        for (int c = 0; c < 4; c++) o[r][c] = 0.f;
    }
    __syncthreads();

    const float scale = 0.125f;  // 1/sqrt(64)

    for (int kt = 0; kt < Tt / BN; kt++) {
        // load K (transposed) and V tiles
        #pragma unroll
        for (int i = 0; i < 16; i++) {
            int idx = tid + i * 256;
            int k = idx & 63, s = idx >> 6;
            ks[k * LDP + s] = g_k[kvbase + (size_t)(kt * BN + s) * Dd + k];
        }
        #pragma unroll
        for (int i = 0; i < 16; i++) {
            int idx = tid + i * 256;
            int d = idx & 63, s = idx >> 6;
            vs[s * LDP + d] = g_v[kvbase + (size_t)(kt * BN + s) * Dd + d];
        }
        __syncthreads();

        // scores: sc[r][c] = q_row(ty*4+r) . k_row(tx*4+c)
        float sc[4][4];
        #pragma unroll
        for (int r = 0; r < 4; r++)
            #pragma unroll
            for (int c = 0; c < 4; c++) sc[r][c] = 0.f;

        const float* qp = qs + ty * 4;
        const float* kp = ks + tx * 4;
        #pragma unroll 8
        for (int k = 0; k < 64; k++) {
            float4 qv = *(const float4*)&qp[k * LDP];
            float4 kv = *(const float4*)&kp[k * LDP];
            float qa[4] = {qv.x, qv.y, qv.z, qv.w};
            float ka[4] = {kv.x, kv.y, kv.z, kv.w};
            #pragma unroll
            for (int r = 0; r < 4; r++)
                #pragma unroll
                for (int c = 0; c < 4; c++) sc[r][c] += qa[r] * ka[c];
        }

        // online softmax per row (row reduction over tx: 16-lane shfl group)
        #pragma unroll
        for (int r = 0; r < 4; r++) {
            float mx = -1e30f;
            #pragma unroll
            for (int c = 0; c < 4; c++) {
                sc[r][c] *= scale;
                mx = fmaxf(mx, sc[r][c]);
            }
            #pragma unroll
            for (int off = 8; off > 0; off >>= 1)
                mx = fmaxf(mx, __shfl_xor_sync(0xffffffffu, mx, off));
            float mnew = fmaxf(mrow[r], mx);
            float corr = __expf(mrow[r] - mnew);
            mrow[r] = mnew;
            float pp[4], psum = 0.f;
            #pragma unroll
            for (int c = 0; c < 4; c++) {
                pp[c] = __expf(sc[r][c] - mnew);
                psum += pp[c];
            }
            #pragma unroll
            for (int off = 8; off > 0; off >>= 1)
                psum += __shfl_xor_sync(0xffffffffu, psum, off);
            lrow[r] = lrow[r] * corr + psum;
            #pragma unroll
            for (int c = 0; c < 4; c++) o[r][c] *= corr;
            // stage P transposed: ps[key][qrow]
            #pragma unroll
            for (int c = 0; c < 4; c++)
                ps[(tx * 4 + c) * LDP + ty * 4 + r] = pp[c];
        }
        __syncthreads();

        // O += P @ V
        const float* pp2 = ps + ty * 4;
        const float* vp  = vs + tx * 4;
        #pragma unroll 8
        for (int s = 0; s < 64; s++) {
            float4 pv = *(const float4*)&pp2[s * LDP];
            float4 vv = *(const float4*)&vp[s * LDP];
            float pa[4] = {pv.x, pv.y, pv.z, pv.w};
            float va[4] = {vv.x, vv.y, vv.z, vv.w};
            #pragma unroll
            for (int r = 0; r < 4; r++)
                #pragma unroll
                for (int c = 0; c < 4; c++) o[r][c] += pa[r] * va[c];
        }
        __syncthreads();
    }

    #pragma unroll
    for (int r = 0; r < 4; r++) {
        float inv = 1.f / lrow[r];
        float4 o4 = make_float4(o[r][0] * inv, o[r][1] * inv,
                                o[r][2] * inv, o[r][3] * inv);
        *(float4*)&out[qbase + (size_t)(ty * 4 + r) * Dd + tx * 4] = o4;
    }
}

// ---------------------------------------------------------------------------
// Inputs (metadata order): x, Wq, bq, Wk, bk, Wv, bv, mask(ignored: False)
// ---------------------------------------------------------------------------
extern "C" void kernel_launch(void* const* d_in, const int* in_sizes, int n_in,
                              void* d_out, int out_size)
{
    const float* x  = (const float*)d_in[0];
    const float* Wq = (const float*)d_in[1];
    const float* bq = (const float*)d_in[2];
    const float* Wk = (const float*)d_in[3];
    const float* bk = (const float*)d_in[4];
    const float* Wv = (const float*)d_in[5];
    const float* bv = (const float*)d_in[6];
    float* out = (float*)d_out;

    cudaFuncSetAttribute(attn_kernel,
                         cudaFuncAttributeMaxDynamicSharedMemorySize, SMEM_ATTN);

    proj_kernel<<<dim3(NROW / RB, 3), 256>>>(x, Wq, bq, Wk, bk, Wv, bv);
    attn_kernel<<<256, 256, SMEM_ATTN>>>(out);
}

// round 4
// speedup vs baseline: 1.1376x; 1.1376x over previous
#include <cuda_runtime.h>

// Problem constants
#define Bb 4
#define Tt 4096
#define Ee 768
#define Dd 64
#define NROW (Bb*Tt)   // 16384

// Scratch for projected Q / K_arg / V_arg
__device__ float g_q[NROW*Dd];
__device__ float g_k[NROW*Dd];
__device__ float g_v[NROW*Dd];

// ---------------------------------------------------------------------------
// Fused projection (unchanged from passing baseline): q=x@Wq+bq,
// k_arg=x@Wv+bv, v_arg=x@Wk+bk (reference swaps K/V weights).
// ---------------------------------------------------------------------------
#define RB 128
#define KC 32

__global__ __launch_bounds__(256) void proj_kernel(
    const float* __restrict__ x,
    const float* __restrict__ Wq, const float* __restrict__ bq,
    const float* __restrict__ Wk, const float* __restrict__ bk,
    const float* __restrict__ Wv, const float* __restrict__ bv)
{
    __shared__ float xs[KC][RB + 4];
    __shared__ float ws[KC][Dd];

    int m = blockIdx.y;
    const float* W    = (m == 0) ? Wq : ((m == 1) ? Wv : Wk);
    const float* bias = (m == 0) ? bq : ((m == 1) ? bv : bk);
    float* out        = (m == 0) ? g_q : ((m == 1) ? g_k : g_v);

    int row0 = blockIdx.x * RB;
    int tid  = threadIdx.x;
    int ty   = tid >> 4;
    int tx   = tid & 15;

    float acc[8][4];
    #pragma unroll
    for (int r = 0; r < 8; r++)
        #pragma unroll
        for (int c = 0; c < 4; c++) acc[r][c] = 0.f;

    for (int e0 = 0; e0 < Ee; e0 += KC) {
        __syncthreads();
        #pragma unroll
        for (int i = 0; i < 16; i++) {
            int idx = tid + i * 256;
            int k   = idx & (KC - 1);
            int row = idx >> 5;
            xs[k][row] = x[(size_t)(row0 + row) * Ee + e0 + k];
        }
        #pragma unroll
        for (int i = 0; i < 8; i++) {
            int idx = tid + i * 256;
            int col = idx & 63;
            int k   = idx >> 6;
            ws[k][col] = W[(size_t)(e0 + k) * Dd + col];
        }
        __syncthreads();
        #pragma unroll
        for (int k = 0; k < KC; k++) {
            float4 wv4 = *(const float4*)&ws[k][tx * 4];
            float4 a0  = *(const float4*)&xs[k][ty * 8];
            float4 a1  = *(const float4*)&xs[k][ty * 8 + 4];
            float a[8] = {a0.x, a0.y, a0.z, a0.w, a1.x, a1.y, a1.z, a1.w};
            #pragma unroll
            for (int r = 0; r < 8; r++) {
                acc[r][0] += a[r] * wv4.x;
                acc[r][1] += a[r] * wv4.y;
                acc[r][2] += a[r] * wv4.z;
                acc[r][3] += a[r] * wv4.w;
            }
        }
    }

    float b0 = bias[tx * 4 + 0], b1 = bias[tx * 4 + 1];
    float b2 = bias[tx * 4 + 2], b3 = bias[tx * 4 + 3];
    #pragma unroll
    for (int r = 0; r < 8; r++) {
        float4 o4 = make_float4(acc[r][0] + b0, acc[r][1] + b1,
                                acc[r][2] + b2, acc[r][3] + b3);
        *(float4*)&out[(size_t)(row0 + ty * 8 + r) * Dd + tx * 4] = o4;
    }
}

// ---------------------------------------------------------------------------
// Flash attention v2: 128 threads, 8x4 microtile (0.75 B smem / FLOP).
// Grid: 256 blocks (4 batch x 64 row-tiles of 64). Threads: ty=tid>>4 (0..7,
// 8 q-rows each), tx=tid&15 (4 keys / 4 d-cols each).
// ---------------------------------------------------------------------------
#define BM 64
#define BN 64
#define LDP 68
#define SMEM_ATTN (4 * 64 * LDP * 4)   // 69632 bytes

__global__ __launch_bounds__(128) void attn_kernel(float* __restrict__ out)
{
    extern __shared__ float sm[];
    float* qs = sm;                 // [64 k][LDP]  qs[k*LDP + row]   (transposed)
    float* ks = qs + 64 * LDP;      // [64 k][LDP]  ks[k*LDP + key]   (transposed)
    float* vs = ks + 64 * LDP;      // [64 s][LDP]  vs[s*LDP + d]
    float* ps = vs + 64 * LDP;      // [64 key][LDP] ps[key*LDP + row] (transposed)

    int bx    = blockIdx.x;
    int batch = bx >> 6;
    int row0  = (bx & 63) * BM;
    size_t qbase  = ((size_t)batch * Tt + row0) * Dd;
    size_t kvbase = (size_t)batch * Tt * Dd;

    int tid = threadIdx.x;
    int ty  = tid >> 4;   // 0..7  -> 8 q-rows
    int tx  = tid & 15;   // 0..15 -> 4 keys / 4 d

    // load Q tile transposed (4096 elems / 128 thr = 32 each; coalesced)
    #pragma unroll
    for (int i = 0; i < 32; i++) {
        int idx = tid + i * 128;
        int k = idx & 63, r = idx >> 6;
        qs[k * LDP + r] = g_q[qbase + (size_t)r * Dd + k];
    }

    float o[8][4], mrow[8], lrow[8];
    #pragma unroll
    for (int r = 0; r < 8; r++) {
        mrow[r] = -1e30f; lrow[r] = 0.f;
        #pragma unroll
        for (int c = 0; c < 4; c++) o[r][c] = 0.f;
    }
    __syncthreads();

    const float scale = 0.125f;  // 1/sqrt(64)

    for (int kt = 0; kt < Tt / BN; kt++) {
        // load K (transposed) and V tiles
        #pragma unroll
        for (int i = 0; i < 32; i++) {
            int idx = tid + i * 128;
            int k = idx & 63, s = idx >> 6;
            ks[k * LDP + s] = g_k[kvbase + (size_t)(kt * BN + s) * Dd + k];
        }
        #pragma unroll
        for (int i = 0; i < 32; i++) {
            int idx = tid + i * 128;
            int d = idx & 63, s = idx >> 6;
            vs[s * LDP + d] = g_v[kvbase + (size_t)(kt * BN + s) * Dd + d];
        }
        __syncthreads();

        // scores: sc[r][c] = q_row(ty*8+r) . k_row(tx*4+c)
        float sc[8][4];
        #pragma unroll
        for (int r = 0; r < 8; r++)
            #pragma unroll
            for (int c = 0; c < 4; c++) sc[r][c] = 0.f;

        const float* qp = qs + ty * 8;
        const float* kp = ks + tx * 4;
        #pragma unroll 4
        for (int k = 0; k < 64; k++) {
            float4 q0 = *(const float4*)&qp[k * LDP];
            float4 q1 = *(const float4*)&qp[k * LDP + 4];
            float4 kv = *(const float4*)&kp[k * LDP];
            float qa[8] = {q0.x, q0.y, q0.z, q0.w, q1.x, q1.y, q1.z, q1.w};
            float ka[4] = {kv.x, kv.y, kv.z, kv.w};
            #pragma unroll
            for (int r = 0; r < 8; r++)
                #pragma unroll
                for (int c = 0; c < 4; c++) sc[r][c] += qa[r] * ka[c];
        }

        // online softmax per row (16-lane shfl groups); sc becomes exp(P)
        #pragma unroll
        for (int r = 0; r < 8; r++) {
            float mx = -1e30f;
            #pragma unroll
            for (int c = 0; c < 4; c++) {
                sc[r][c] *= scale;
                mx = fmaxf(mx, sc[r][c]);
            }
            #pragma unroll
            for (int off = 8; off > 0; off >>= 1)
                mx = fmaxf(mx, __shfl_xor_sync(0xffffffffu, mx, off));
            float mnew = fmaxf(mrow[r], mx);
            float corr = __expf(mrow[r] - mnew);
            mrow[r] = mnew;
            float psum = 0.f;
            #pragma unroll
            for (int c = 0; c < 4; c++) {
                sc[r][c] = __expf(sc[r][c] - mnew);
                psum += sc[r][c];
            }
            #pragma unroll
            for (int off = 8; off > 0; off >>= 1)
                psum += __shfl_xor_sync(0xffffffffu, psum, off);
            lrow[r] = lrow[r] * corr + psum;
            #pragma unroll
            for (int c = 0; c < 4; c++) o[r][c] *= corr;
        }
        // stage P transposed with vector stores: ps[key][row]
        #pragma unroll
        for (int c = 0; c < 4; c++) {
            float* pd = ps + (tx * 4 + c) * LDP + ty * 8;
            *(float4*)&pd[0] = make_float4(sc[0][c], sc[1][c], sc[2][c], sc[3][c]);
            *(float4*)&pd[4] = make_float4(sc[4][c], sc[5][c], sc[6][c], sc[7][c]);
        }
        __syncthreads();

        // O += P @ V
        const float* pp2 = ps + ty * 8;
        const float* vp  = vs + tx * 4;
        #pragma unroll 4
        for (int s = 0; s < 64; s++) {
            float4 p0 = *(const float4*)&pp2[s * LDP];
            float4 p1 = *(const float4*)&pp2[s * LDP + 4];
            float4 vv = *(const float4*)&vp[s * LDP];
            float pa[8] = {p0.x, p0.y, p0.z, p0.w, p1.x, p1.y, p1.z, p1.w};
            float va[4] = {vv.x, vv.y, vv.z, vv.w};
            #pragma unroll
            for (int r = 0; r < 8; r++)
                #pragma unroll
                for (int c = 0; c < 4; c++) o[r][c] += pa[r] * va[c];
        }
        __syncthreads();
    }

    #pragma unroll
    for (int r = 0; r < 8; r++) {
        float inv = 1.f / lrow[r];
        float4 o4 = make_float4(o[r][0] * inv, o[r][1] * inv,
                                o[r][2] * inv, o[r][3] * inv);
        *(float4*)&out[qbase + (size_t)(ty * 8 + r) * Dd + tx * 4] = o4;
    }
}

// ---------------------------------------------------------------------------
// Inputs (metadata order): x, Wq, bq, Wk, bk, Wv, bv, mask(ignored: False)
// ---------------------------------------------------------------------------
extern "C" void kernel_launch(void* const* d_in, const int* in_sizes, int n_in,
                              void* d_out, int out_size)
{
    const float* x  = (const float*)d_in[0];
    const float* Wq = (const float*)d_in[1];
    const float* bq = (const float*)d_in[2];
    const float* Wk = (const float*)d_in[3];
    const float* bk = (const float*)d_in[4];
    const float* Wv = (const float*)d_in[5];
    const float* bv = (const float*)d_in[6];
    float* out = (float*)d_out;

    cudaFuncSetAttribute(attn_kernel,
                         cudaFuncAttributeMaxDynamicSharedMemorySize, SMEM_ATTN);

    proj_kernel<<<dim3(NROW / RB, 3), 256>>>(x, Wq, bq, Wk, bk, Wv, bv);
    attn_kernel<<<256, 128, SMEM_ATTN>>>(out);
}

// round 5
// speedup vs baseline: 2.2275x; 1.9582x over previous
#include <cuda_runtime.h>
#include <cstdint>

// Problem constants
#define Bb 4
#define Tt 4096
#define Ee 768
#define Dd 64
#define NROW (Bb*Tt)   // 16384

// Scratch for projected Q / K_arg / V_arg (tf32-rounded fp32 values)
__device__ float g_q[NROW*Dd];
__device__ float g_k[NROW*Dd];
__device__ float g_v[NROW*Dd];

// ---------------------------------------------------------------------------
// helpers
// ---------------------------------------------------------------------------
__device__ __forceinline__ uint32_t f2tf(float f) {
    uint32_t u; asm("cvt.rna.tf32.f32 %0, %1;" : "=r"(u) : "f"(f)); return u;
}
__device__ __forceinline__ float ex2f(float x) {
    float y; asm("ex2.approx.f32 %0, %1;" : "=f"(y) : "f"(x)); return y;
}
__device__ __forceinline__ void mma_tf32(float* c, const uint32_t* a,
                                         uint32_t b0, uint32_t b1) {
    asm("mma.sync.aligned.m16n8k8.row.col.f32.tf32.tf32.f32 "
        "{%0,%1,%2,%3}, {%4,%5,%6,%7}, {%8,%9}, {%0,%1,%2,%3};"
        : "+f"(c[0]), "+f"(c[1]), "+f"(c[2]), "+f"(c[3])
        : "r"(a[0]), "r"(a[1]), "r"(a[2]), "r"(a[3]), "r"(b0), "r"(b1));
}

// ---------------------------------------------------------------------------
// Fused projection: q=x@Wq+bq, k_arg=x@Wv+bv, v_arg=x@Wk+bk (reference swaps
// K/V weights). Epilogue rounds outputs to tf32 (rna) so the attention MMA
// consumes unbiased tf32 operands.
// ---------------------------------------------------------------------------
#define RB 128
#define KC 32

__global__ __launch_bounds__(256) void proj_kernel(
    const float* __restrict__ x,
    const float* __restrict__ Wq, const float* __restrict__ bq,
    const float* __restrict__ Wk, const float* __restrict__ bk,
    const float* __restrict__ Wv, const float* __restrict__ bv)
{
    __shared__ float xs[KC][RB + 4];
    __shared__ float ws[KC][Dd];

    int m = blockIdx.y;
    const float* W    = (m == 0) ? Wq : ((m == 1) ? Wv : Wk);
    const float* bias = (m == 0) ? bq : ((m == 1) ? bv : bk);
    float* out        = (m == 0) ? g_q : ((m == 1) ? g_k : g_v);

    int row0 = blockIdx.x * RB;
    int tid  = threadIdx.x;
    int ty   = tid >> 4;
    int tx   = tid & 15;

    float acc[8][4];
    #pragma unroll
    for (int r = 0; r < 8; r++)
        #pragma unroll
        for (int c = 0; c < 4; c++) acc[r][c] = 0.f;

    for (int e0 = 0; e0 < Ee; e0 += KC) {
        __syncthreads();
        #pragma unroll
        for (int i = 0; i < 16; i++) {
            int idx = tid + i * 256;
            int k   = idx & (KC - 1);
            int row = idx >> 5;
            xs[k][row] = x[(size_t)(row0 + row) * Ee + e0 + k];
        }
        #pragma unroll
        for (int i = 0; i < 8; i++) {
            int idx = tid + i * 256;
            int col = idx & 63;
            int k   = idx >> 6;
            ws[k][col] = W[(size_t)(e0 + k) * Dd + col];
        }
        __syncthreads();
        #pragma unroll
        for (int k = 0; k < KC; k++) {
            float4 wv4 = *(const float4*)&ws[k][tx * 4];
            float4 a0  = *(const float4*)&xs[k][ty * 8];
            float4 a1  = *(const float4*)&xs[k][ty * 8 + 4];
            float a[8] = {a0.x, a0.y, a0.z, a0.w, a1.x, a1.y, a1.z, a1.w};
            #pragma unroll
            for (int r = 0; r < 8; r++) {
                acc[r][0] += a[r] * wv4.x;
                acc[r][1] += a[r] * wv4.y;
                acc[r][2] += a[r] * wv4.z;
                acc[r][3] += a[r] * wv4.w;
            }
        }
    }

    float b0 = bias[tx * 4 + 0], b1 = bias[tx * 4 + 1];
    float b2 = bias[tx * 4 + 2], b3 = bias[tx * 4 + 3];
    #pragma unroll
    for (int r = 0; r < 8; r++) {
        float4 o4 = make_float4(
            __uint_as_float(f2tf(acc[r][0] + b0)),
            __uint_as_float(f2tf(acc[r][1] + b1)),
            __uint_as_float(f2tf(acc[r][2] + b2)),
            __uint_as_float(f2tf(acc[r][3] + b3)));
        *(float4*)&out[(size_t)(row0 + ty * 8 + r) * Dd + tx * 4] = o4;
    }
}

// ---------------------------------------------------------------------------
// Flash attention v3: tf32 mma.sync. 4 warps, each owns 16 q-rows x 64 keys.
// Q fragments register-resident; S/O in mma accumulators; P staged through a
// warp-private smem buffer (syncwarp only). Padded layouts: all fragment LDS
// patterns bank-conflict-free (LDK=68: 4g+t; LDV=72: 8t+g).
// ---------------------------------------------------------------------------
#define LDK 68
#define LDV 72
#define LDQ 68
#define SMEM_ATTN ((64*LDK + 64*LDV + 4*16*LDQ) * 4)   // 53248 bytes

__global__ __launch_bounds__(128) void attn_kernel(float* __restrict__ out)
{
    extern __shared__ float sm[];
    float* ks = sm;                  // [64 keys][LDK]
    float* vs = ks + 64 * LDK;       // [64 keys][LDV]
    float* pq = vs + 64 * LDV;       // 4 x [16 rows][LDQ]  (Q staging, then P)

    int bx    = blockIdx.x;
    int batch = bx >> 6;
    int row0  = (bx & 63) * 64;
    size_t qbase  = ((size_t)batch * Tt + row0) * Dd;
    size_t kvbase = (size_t)batch * Tt * Dd;

    int tid  = threadIdx.x;
    int wid  = tid >> 5;
    int lane = tid & 31;
    int g = lane >> 2, t = lane & 3;
    float* pw = pq + wid * (16 * LDQ);

    // stage Q tile (coalesced), then pick up register fragments
    {
        const float4* gq = (const float4*)(g_q + qbase);
        #pragma unroll
        for (int i = 0; i < 8; i++) {
            int idx = tid + i * 128;
            int r = idx >> 4, c4 = idx & 15;
            *(float4*)&pq[(r >> 4) * (16 * LDQ) + (r & 15) * LDQ + c4 * 4] = gq[idx];
        }
    }
    __syncthreads();

    uint32_t qf[8][4];
    #pragma unroll
    for (int jk = 0; jk < 8; jk++) {
        qf[jk][0] = __float_as_uint(pw[ g      * LDQ + 8 * jk + t    ]);
        qf[jk][1] = __float_as_uint(pw[(g + 8) * LDQ + 8 * jk + t    ]);
        qf[jk][2] = __float_as_uint(pw[ g      * LDQ + 8 * jk + t + 4]);
        qf[jk][3] = __float_as_uint(pw[(g + 8) * LDQ + 8 * jk + t + 4]);
    }

    float of[8][4];
    #pragma unroll
    for (int jn = 0; jn < 8; jn++)
        #pragma unroll
        for (int c = 0; c < 4; c++) of[jn][c] = 0.f;

    float m_lo = -1e30f, m_hi = -1e30f, l_lo = 0.f, l_hi = 0.f;
    const float cl = 0.125f * 1.44269504f;   // scale * log2(e)

    for (int kt = 0; kt < Tt / 64; kt++) {
        const float4* gk = (const float4*)(g_k + kvbase + (size_t)kt * 64 * Dd);
        const float4* gv = (const float4*)(g_v + kvbase + (size_t)kt * 64 * Dd);
        #pragma unroll
        for (int i = 0; i < 8; i++) {
            int idx = tid + i * 128;
            int s = idx >> 4, c4 = idx & 15;
            *(float4*)&ks[s * LDK + c4 * 4] = gk[idx];
            *(float4*)&vs[s * LDV + c4 * 4] = gv[idx];
        }
        __syncthreads();

        // S = Q @ K^T   (A=Q frags in regs, B from ks)
        float sf[8][4];
        #pragma unroll
        for (int jn = 0; jn < 8; jn++)
            #pragma unroll
            for (int c = 0; c < 4; c++) sf[jn][c] = 0.f;

        #pragma unroll
        for (int jk = 0; jk < 8; jk++) {
            #pragma unroll
            for (int jn = 0; jn < 8; jn++) {
                const float* kb = &ks[(8 * jn + g) * LDK + 8 * jk + t];
                mma_tf32(sf[jn], qf[jk],
                         __float_as_uint(kb[0]), __float_as_uint(kb[4]));
            }
        }

        // online softmax in log2 domain (quad = 4 lanes share rows g,g+8)
        float mx_lo = -1e30f, mx_hi = -1e30f;
        #pragma unroll
        for (int jn = 0; jn < 8; jn++) {
            sf[jn][0] *= cl; sf[jn][1] *= cl; sf[jn][2] *= cl; sf[jn][3] *= cl;
            mx_lo = fmaxf(mx_lo, fmaxf(sf[jn][0], sf[jn][1]));
            mx_hi = fmaxf(mx_hi, fmaxf(sf[jn][2], sf[jn][3]));
        }
        mx_lo = fmaxf(mx_lo, __shfl_xor_sync(0xffffffffu, mx_lo, 1));
        mx_lo = fmaxf(mx_lo, __shfl_xor_sync(0xffffffffu, mx_lo, 2));
        mx_hi = fmaxf(mx_hi, __shfl_xor_sync(0xffffffffu, mx_hi, 1));
        mx_hi = fmaxf(mx_hi, __shfl_xor_sync(0xffffffffu, mx_hi, 2));

        float mn_lo = fmaxf(m_lo, mx_lo), mn_hi = fmaxf(m_hi, mx_hi);
        float corr_lo = ex2f(m_lo - mn_lo), corr_hi = ex2f(m_hi - mn_hi);
        m_lo = mn_lo; m_hi = mn_hi;

        float ps_lo = 0.f, ps_hi = 0.f;
        #pragma unroll
        for (int jn = 0; jn < 8; jn++) {
            float p0 = ex2f(sf[jn][0] - mn_lo);
            float p1 = ex2f(sf[jn][1] - mn_lo);
            float p2 = ex2f(sf[jn][2] - mn_hi);
            float p3 = ex2f(sf[jn][3] - mn_hi);
            ps_lo += p0 + p1;  ps_hi += p2 + p3;
            uint2 u01 = make_uint2(f2tf(p0), f2tf(p1));
            uint2 u23 = make_uint2(f2tf(p2), f2tf(p3));
            *(uint2*)&pw[ g      * LDQ + 8 * jn + 2 * t] = u01;
            *(uint2*)&pw[(g + 8) * LDQ + 8 * jn + 2 * t] = u23;
        }
        ps_lo += __shfl_xor_sync(0xffffffffu, ps_lo, 1);
        ps_lo += __shfl_xor_sync(0xffffffffu, ps_lo, 2);
        ps_hi += __shfl_xor_sync(0xffffffffu, ps_hi, 1);
        ps_hi += __shfl_xor_sync(0xffffffffu, ps_hi, 2);
        l_lo = l_lo * corr_lo + ps_lo;
        l_hi = l_hi * corr_hi + ps_hi;

        #pragma unroll
        for (int jn = 0; jn < 8; jn++) {
            of[jn][0] *= corr_lo; of[jn][1] *= corr_lo;
            of[jn][2] *= corr_hi; of[jn][3] *= corr_hi;
        }
        __syncwarp();

        // O += P @ V   (A=P from pw, B from vs)
        #pragma unroll
        for (int jk = 0; jk < 8; jk++) {
            uint32_t af[4];
            af[0] = __float_as_uint(pw[ g      * LDQ + 8 * jk + t    ]);
            af[1] = __float_as_uint(pw[(g + 8) * LDQ + 8 * jk + t    ]);
            af[2] = __float_as_uint(pw[ g      * LDQ + 8 * jk + t + 4]);
            af[3] = __float_as_uint(pw[(g + 8) * LDQ + 8 * jk + t + 4]);
            #pragma unroll
            for (int jn = 0; jn < 8; jn++) {
                const float* vb = &vs[(8 * jk + t) * LDV + 8 * jn + g];
                mma_tf32(of[jn], af,
                         __float_as_uint(vb[0]), __float_as_uint(vb[4 * LDV]));
            }
        }
        __syncthreads();
    }

    float il_lo = 1.f / l_lo, il_hi = 1.f / l_hi;
    #pragma unroll
    for (int jn = 0; jn < 8; jn++) {
        float2 r01 = make_float2(of[jn][0] * il_lo, of[jn][1] * il_lo);
        float2 r23 = make_float2(of[jn][2] * il_hi, of[jn][3] * il_hi);
        *(float2*)&out[qbase + (size_t)(wid * 16 + g    ) * Dd + 8 * jn + 2 * t] = r01;
        *(float2*)&out[qbase + (size_t)(wid * 16 + g + 8) * Dd + 8 * jn + 2 * t] = r23;
    }
}

// ---------------------------------------------------------------------------
// Inputs (metadata order): x, Wq, bq, Wk, bk, Wv, bv, mask(ignored: False)
// ---------------------------------------------------------------------------
extern "C" void kernel_launch(void* const* d_in, const int* in_sizes, int n_in,
                              void* d_out, int out_size)
{
    const float* x  = (const float*)d_in[0];
    const float* Wq = (const float*)d_in[1];
    const float* bq = (const float*)d_in[2];
    const float* Wk = (const float*)d_in[3];
    const float* bk = (const float*)d_in[4];
    const float* Wv = (const float*)d_in[5];
    const float* bv = (const float*)d_in[6];
    float* out = (float*)d_out;

    cudaFuncSetAttribute(attn_kernel,
                         cudaFuncAttributeMaxDynamicSharedMemorySize, SMEM_ATTN);

    proj_kernel<<<dim3(NROW / RB, 3), 256>>>(x, Wq, bq, Wk, bk, Wv, bv);
    attn_kernel<<<256, 128, SMEM_ATTN>>>(out);
}

// round 6
// speedup vs baseline: 3.5683x; 1.6019x over previous
#include <cuda_runtime.h>
#include <cstdint>

// Problem constants
#define Bb 4
#define Tt 4096
#define Ee 768
#define Dd 64
#define NROW (Bb*Tt)   // 16384

// Scratch for projected Q / K_arg / V_arg (tf32-rounded fp32 values)
__device__ float g_q[NROW*Dd];
__device__ float g_k[NROW*Dd];
__device__ float g_v[NROW*Dd];

// ---------------------------------------------------------------------------
// helpers
// ---------------------------------------------------------------------------
__device__ __forceinline__ uint32_t f2tf(float f) {
    uint32_t u; asm("cvt.rna.tf32.f32 %0, %1;" : "=r"(u) : "f"(f)); return u;
}
__device__ __forceinline__ float tfv(float f) {   // value rounded to tf32
    return __uint_as_float(f2tf(f));
}
__device__ __forceinline__ float ex2f(float x) {
    float y; asm("ex2.approx.f32 %0, %1;" : "=f"(y) : "f"(x)); return y;
}
__device__ __forceinline__ void mma_tf32(float* c, const uint32_t* a,
                                         uint32_t b0, uint32_t b1) {
    asm("mma.sync.aligned.m16n8k8.row.col.f32.tf32.tf32.f32 "
        "{%0,%1,%2,%3}, {%4,%5,%6,%7}, {%8,%9}, {%0,%1,%2,%3};"
        : "+f"(c[0]), "+f"(c[1]), "+f"(c[2]), "+f"(c[3])
        : "r"(a[0]), "r"(a[1]), "r"(a[2]), "r"(a[3]), "r"(b0), "r"(b1));
}
__device__ __forceinline__ void cpa16(uint32_t s, const float* g) {
    asm volatile("cp.async.cg.shared.global [%0], [%1], 16;" :: "r"(s), "l"(g));
}

// ---------------------------------------------------------------------------
// Projection via tf32 mma: q=x@Wq+bq, k_arg=x@Wv+bv, v_arg=x@Wk+bk
// (reference swaps K/V weights). 128 threads / 4 warps; warp owns 32 rows x 64
// cols. K staged 32 at a time. smem stride 36 -> fragment LDS banks = 4g+t
// (conflict-free). Operands rounded to tf32 at smem-store time.
// ---------------------------------------------------------------------------
#define RB 128
#define LDX 36

__global__ __launch_bounds__(128) void proj_kernel(
    const float* __restrict__ x,
    const float* __restrict__ Wq, const float* __restrict__ bq,
    const float* __restrict__ Wk, const float* __restrict__ bk,
    const float* __restrict__ Wv, const float* __restrict__ bv)
{
    __shared__ float xs[RB * LDX];   // [row][k] 128x32 (+pad)
    __shared__ float ws[64 * LDX];   // [col][k] 64x32 (+pad), transposed W

    int m = blockIdx.y;
    const float* W    = (m == 0) ? Wq : ((m == 1) ? Wv : Wk);
    const float* bias = (m == 0) ? bq : ((m == 1) ? bv : bk);
    float* out        = (m == 0) ? g_q : ((m == 1) ? g_k : g_v);

    int row0 = blockIdx.x * RB;
    int tid  = threadIdx.x;
    int wid  = tid >> 5;
    int lane = tid & 31;
    int g = lane >> 2, t = lane & 3;
    int wm = wid * 32;

    float acc[2][8][4];
    #pragma unroll
    for (int jm = 0; jm < 2; jm++)
        #pragma unroll
        for (int jn = 0; jn < 8; jn++)
            #pragma unroll
            for (int c = 0; c < 4; c++) acc[jm][jn][c] = 0.f;

    int wcol = tid & 63, wkh = (tid >> 6) * 16;

    for (int e0 = 0; e0 < Ee; e0 += 32) {
        __syncthreads();
        // x chunk: 128 rows x 32 k, tf32-rounded
        #pragma unroll
        for (int i = 0; i < 8; i++) {
            int idx = tid + i * 128;          // float4 index, 1024 total
            int row = idx >> 3, k4 = idx & 7;
            float4 v = *(const float4*)&x[(size_t)(row0 + row) * Ee + e0 + k4 * 4];
            v.x = tfv(v.x); v.y = tfv(v.y); v.z = tfv(v.z); v.w = tfv(v.w);
            *(float4*)&xs[row * LDX + k4 * 4] = v;
        }
        // W chunk transposed: ws[col][k], tf32-rounded
        #pragma unroll
        for (int j = 0; j < 16; j++)
            ws[wcol * LDX + wkh + j] = tfv(W[(size_t)(e0 + wkh + j) * Dd + wcol]);
        __syncthreads();

        #pragma unroll
        for (int ks8 = 0; ks8 < 4; ks8++) {
            int k0 = ks8 * 8;
            uint32_t af[2][4];
            #pragma unroll
            for (int jm = 0; jm < 2; jm++) {
                int base = wm + jm * 16;
                af[jm][0] = __float_as_uint(xs[(base + g    ) * LDX + k0 + t    ]);
                af[jm][1] = __float_as_uint(xs[(base + g + 8) * LDX + k0 + t    ]);
                af[jm][2] = __float_as_uint(xs[(base + g    ) * LDX + k0 + t + 4]);
                af[jm][3] = __float_as_uint(xs[(base + g + 8) * LDX + k0 + t + 4]);
            }
            #pragma unroll
            for (int jn = 0; jn < 8; jn++) {
                uint32_t b0 = __float_as_uint(ws[(jn * 8 + g) * LDX + k0 + t    ]);
                uint32_t b1 = __float_as_uint(ws[(jn * 8 + g) * LDX + k0 + t + 4]);
                mma_tf32(acc[0][jn], af[0], b0, b1);
                mma_tf32(acc[1][jn], af[1], b0, b1);
            }
        }
    }

    #pragma unroll
    for (int jn = 0; jn < 8; jn++) {
        float b0v = bias[jn * 8 + 2 * t], b1v = bias[jn * 8 + 2 * t + 1];
        #pragma unroll
        for (int jm = 0; jm < 2; jm++) {
            int row = row0 + wm + jm * 16;
            float2 lo = make_float2(tfv(acc[jm][jn][0] + b0v),
                                    tfv(acc[jm][jn][1] + b1v));
            float2 hi = make_float2(tfv(acc[jm][jn][2] + b0v),
                                    tfv(acc[jm][jn][3] + b1v));
            *(float2*)&out[(size_t)(row + g    ) * Dd + jn * 8 + 2 * t] = lo;
            *(float2*)&out[(size_t)(row + g + 8) * Dd + jn * 8 + 2 * t] = hi;
        }
    }
}

// ---------------------------------------------------------------------------
// Flash attention v4: tf32 mma + cp.async double-buffered K/V tiles.
// 4 warps, each owns 16 q-rows x 64 keys; Q frags register-resident; S/O in
// accumulators; P via warp-private smem. Stage layout per stage: K[64][LDK],
// V[64][LDV]; two stages + P buffer.
// ---------------------------------------------------------------------------
#define LDK 68
#define LDV 72
#define LDQ 68
#define SKV (64*LDK + 64*LDV)                       // floats per stage
#define SMEM_ATTN ((2*SKV + 4*16*LDQ) * 4)          // 89088 bytes

__global__ __launch_bounds__(128) void attn_kernel(float* __restrict__ out)
{
    extern __shared__ float sm[];
    float* pq = sm + 2 * SKV;                        // 4 x [16][LDQ]
    uint32_t sb = (uint32_t)__cvta_generic_to_shared(sm);

    int bx    = blockIdx.x;
    int batch = bx >> 6;
    int row0  = (bx & 63) * 64;
    size_t qbase  = ((size_t)batch * Tt + row0) * Dd;
    size_t kvbase = (size_t)batch * Tt * Dd;

    int tid  = threadIdx.x;
    int wid  = tid >> 5;
    int lane = tid & 31;
    int g = lane >> 2, t = lane & 3;
    float* pw = pq + wid * (16 * LDQ);

    // prologue: async-issue tile 0 into stage 0
    {
        const float* gk = g_k + kvbase;
        const float* gv = g_v + kvbase;
        #pragma unroll
        for (int i = 0; i < 8; i++) {
            int idx = tid + i * 128;
            int s = idx >> 4, c4 = idx & 15;
            cpa16(sb + (s * LDK + c4 * 4) * 4, gk + idx * 4);
            cpa16(sb + (64 * LDK + s * LDV + c4 * 4) * 4, gv + idx * 4);
        }
        asm volatile("cp.async.commit_group;");
    }

    // stage Q tile, pick up register fragments
    {
        const float4* gq = (const float4*)(g_q + qbase);
        #pragma unroll
        for (int i = 0; i < 8; i++) {
            int idx = tid + i * 128;
            int r = idx >> 4, c4 = idx & 15;
            *(float4*)&pq[(r >> 4) * (16 * LDQ) + (r & 15) * LDQ + c4 * 4] = gq[idx];
        }
    }
    __syncthreads();

    uint32_t qf[8][4];
    #pragma unroll
    for (int jk = 0; jk < 8; jk++) {
        qf[jk][0] = __float_as_uint(pw[ g      * LDQ + 8 * jk + t    ]);
        qf[jk][1] = __float_as_uint(pw[(g + 8) * LDQ + 8 * jk + t    ]);
        qf[jk][2] = __float_as_uint(pw[ g      * LDQ + 8 * jk + t + 4]);
        qf[jk][3] = __float_as_uint(pw[(g + 8) * LDQ + 8 * jk + t + 4]);
    }

    float of[8][4];
    #pragma unroll
    for (int jn = 0; jn < 8; jn++)
        #pragma unroll
        for (int c = 0; c < 4; c++) of[jn][c] = 0.f;

    float m_lo = -1e30f, m_hi = -1e30f, l_lo = 0.f, l_hi = 0.f;
    const float cl = 0.125f * 1.44269504f;   // scale * log2(e)

    for (int kt = 0; kt < Tt / 64; kt++) {
        if (kt + 1 < Tt / 64) {
            // issue next tile into the other stage
            uint32_t stb = sb + ((kt + 1) & 1) * (SKV * 4);
            const float* gk = g_k + kvbase + (size_t)(kt + 1) * 64 * Dd;
            const float* gv = g_v + kvbase + (size_t)(kt + 1) * 64 * Dd;
            #pragma unroll
            for (int i = 0; i < 8; i++) {
                int idx = tid + i * 128;
                int s = idx >> 4, c4 = idx & 15;
                cpa16(stb + (s * LDK + c4 * 4) * 4, gk + idx * 4);
                cpa16(stb + (64 * LDK + s * LDV + c4 * 4) * 4, gv + idx * 4);
            }
            asm volatile("cp.async.commit_group;");
            asm volatile("cp.async.wait_group 1;");
        } else {
            asm volatile("cp.async.wait_group 0;");
        }
        __syncthreads();

        const float* ks = sm + (kt & 1) * SKV;
        const float* vs = ks + 64 * LDK;

        // S = Q @ K^T
        float sf[8][4];
        #pragma unroll
        for (int jn = 0; jn < 8; jn++)
            #pragma unroll
            for (int c = 0; c < 4; c++) sf[jn][c] = 0.f;

        #pragma unroll
        for (int jk = 0; jk < 8; jk++) {
            #pragma unroll
            for (int jn = 0; jn < 8; jn++) {
                const float* kb = &ks[(8 * jn + g) * LDK + 8 * jk + t];
                mma_tf32(sf[jn], qf[jk],
                         __float_as_uint(kb[0]), __float_as_uint(kb[4]));
            }
        }

        // online softmax in log2 domain (quad shares rows g, g+8)
        float mx_lo = -1e30f, mx_hi = -1e30f;
        #pragma unroll
        for (int jn = 0; jn < 8; jn++) {
            sf[jn][0] *= cl; sf[jn][1] *= cl; sf[jn][2] *= cl; sf[jn][3] *= cl;
            mx_lo = fmaxf(mx_lo, fmaxf(sf[jn][0], sf[jn][1]));
            mx_hi = fmaxf(mx_hi, fmaxf(sf[jn][2], sf[jn][3]));
        }
        mx_lo = fmaxf(mx_lo, __shfl_xor_sync(0xffffffffu, mx_lo, 1));
        mx_lo = fmaxf(mx_lo, __shfl_xor_sync(0xffffffffu, mx_lo, 2));
        mx_hi = fmaxf(mx_hi, __shfl_xor_sync(0xffffffffu, mx_hi, 1));
        mx_hi = fmaxf(mx_hi, __shfl_xor_sync(0xffffffffu, mx_hi, 2));

        float mn_lo = fmaxf(m_lo, mx_lo), mn_hi = fmaxf(m_hi, mx_hi);
        float corr_lo = ex2f(m_lo - mn_lo), corr_hi = ex2f(m_hi - mn_hi);
        m_lo = mn_lo; m_hi = mn_hi;

        float ps_lo = 0.f, ps_hi = 0.f;
        #pragma unroll
        for (int jn = 0; jn < 8; jn++) {
            float p0 = ex2f(sf[jn][0] - mn_lo);
            float p1 = ex2f(sf[jn][1] - mn_lo);
            float p2 = ex2f(sf[jn][2] - mn_hi);
            float p3 = ex2f(sf[jn][3] - mn_hi);
            ps_lo += p0 + p1;  ps_hi += p2 + p3;
            uint2 u01 = make_uint2(f2tf(p0), f2tf(p1));
            uint2 u23 = make_uint2(f2tf(p2), f2tf(p3));
            *(uint2*)&pw[ g      * LDQ + 8 * jn + 2 * t] = u01;
            *(uint2*)&pw[(g + 8) * LDQ + 8 * jn + 2 * t] = u23;
        }
        ps_lo += __shfl_xor_sync(0xffffffffu, ps_lo, 1);
        ps_lo += __shfl_xor_sync(0xffffffffu, ps_lo, 2);
        ps_hi += __shfl_xor_sync(0xffffffffu, ps_hi, 1);
        ps_hi += __shfl_xor_sync(0xffffffffu, ps_hi, 2);
        l_lo = l_lo * corr_lo + ps_lo;
        l_hi = l_hi * corr_hi + ps_hi;

        #pragma unroll
        for (int jn = 0; jn < 8; jn++) {
            of[jn][0] *= corr_lo; of[jn][1] *= corr_lo;
            of[jn][2] *= corr_hi; of[jn][3] *= corr_hi;
        }
        __syncwarp();

        // O += P @ V
        #pragma unroll
        for (int jk = 0; jk < 8; jk++) {
            uint32_t af[4];
            af[0] = __float_as_uint(pw[ g      * LDQ + 8 * jk + t    ]);
            af[1] = __float_as_uint(pw[(g + 8) * LDQ + 8 * jk + t    ]);
            af[2] = __float_as_uint(pw[ g      * LDQ + 8 * jk + t + 4]);
            af[3] = __float_as_uint(pw[(g + 8) * LDQ + 8 * jk + t + 4]);
            #pragma unroll
            for (int jn = 0; jn < 8; jn++) {
                const float* vb = &vs[(8 * jk + t) * LDV + 8 * jn + g];
                mma_tf32(of[jn], af,
                         __float_as_uint(vb[0]), __float_as_uint(vb[4 * LDV]));
            }
        }
        __syncthreads();
    }

    float il_lo = 1.f / l_lo, il_hi = 1.f / l_hi;
    #pragma unroll
    for (int jn = 0; jn < 8; jn++) {
        float2 r01 = make_float2(of[jn][0] * il_lo, of[jn][1] * il_lo);
        float2 r23 = make_float2(of[jn][2] * il_hi, of[jn][3] * il_hi);
        *(float2*)&out[qbase + (size_t)(wid * 16 + g    ) * Dd + 8 * jn + 2 * t] = r01;
        *(float2*)&out[qbase + (size_t)(wid * 16 + g + 8) * Dd + 8 * jn + 2 * t] = r23;
    }
}

// ---------------------------------------------------------------------------
// Inputs (metadata order): x, Wq, bq, Wk, bk, Wv, bv, mask(ignored: False)
// ---------------------------------------------------------------------------
extern "C" void kernel_launch(void* const* d_in, const int* in_sizes, int n_in,
                              void* d_out, int out_size)
{
    const float* x  = (const float*)d_in[0];
    const float* Wq = (const float*)d_in[1];
    const float* bq = (const float*)d_in[2];
    const float* Wk = (const float*)d_in[3];
    const float* bk = (const float*)d_in[4];
    const float* Wv = (const float*)d_in[5];
    const float* bv = (const float*)d_in[6];
    float* out = (float*)d_out;

    cudaFuncSetAttribute(attn_kernel,
                         cudaFuncAttributeMaxDynamicSharedMemorySize, SMEM_ATTN);

    proj_kernel<<<dim3(NROW / RB, 3), 128>>>(x, Wq, bq, Wk, bk, Wv, bv);
    attn_kernel<<<256, 128, SMEM_ATTN>>>(out);
}